// round 9
// baseline (speedup 1.0000x reference)
#include <cuda_runtime.h>

#define N3 262144
#define N2 65536
#define N1 16384

typedef unsigned long long u64;

// ---------------- scratch (allocation-free) ----------------
__device__ float g_x7p[N2 * 16];
__device__ float g_x7 [N2 * 32];
__device__ float g_x6 [N1 * 64];
__device__ float g_x7d[N2 * 32];
__device__ float g_P  [N2 * 288];   // 75MB, reused by every P phase (max = enc2)
__device__ float g_P6 [N3 * 9];     // head partial products

__device__ __forceinline__ u64 pack2(float lo, float hi) {
    u64 r; asm("mov.b64 %0, {%1, %2};" : "=l"(r) : "f"(lo), "f"(hi)); return r;
}
__device__ __forceinline__ void fma2(u64& d, u64 a, u64 b) {
    asm("fma.rn.f32x2 %0, %1, %2, %0;" : "+l"(d) : "l"(a), "l"(b));
}
__device__ __forceinline__ float4 max4(float4 a, float4 b) {
    return make_float4(fmaxf(a.x,b.x), fmaxf(a.y,b.y), fmaxf(a.z,b.z), fmaxf(a.w,b.w));
}

// ---------------- GEMM: P[M x Ntot] = A[M x K] @ B[K x Ntot] ----------------
// B[c][g] = w[g%COUT][(g/COUT)*K + c]   (per-tap weight transpose, built in smem)
// APOOL: A row r = elementwise max of child rows 4r..4r+3 (fused quadpool; inputs >=0).
// Tile: TM=64 x TN=144, 288 threads, 4x8 per thread (f32x2 packed cols),
// register double-buffered k-loop, 2 CTAs/SM.
template<int K, int COUT, bool APOOL>
__global__ __launch_bounds__(288, 2)
void gemm_k(const float* __restrict__ A, const float* __restrict__ w,
            float* __restrict__ P, int Ntot)
{
    extern __shared__ u64 sm64[];
    u64*   As2 = sm64;                      // [K][64] duplicated pairs (a,a)
    float* Bs  = (float*)(sm64 + K * 64);   // [K][144]

    const int tid  = threadIdx.x;
    const int row0 = blockIdx.x * 64;
    const int col0 = blockIdx.y * 144;

    // Stage A transposed + duplicated: As2[c][r] = (A[row0+r][c], same)
    // (A is always our own 16B-aligned scratch buffer -> float4 safe)
    const float4* A4 = reinterpret_cast<const float4*>(A);
    const int KC4 = K / 4;
    for (int idx = tid; idx < 64 * KC4; idx += 288) {
        int r = idx / KC4, c4 = idx % KC4;
        float4 v;
        if (APOOL) {
            size_t base = (size_t)(row0 + r) * 4 * KC4 + c4;
            v = __ldg(A4 + base);
            v = max4(v, __ldg(A4 + base + KC4));
            v = max4(v, __ldg(A4 + base + 2 * KC4));
            v = max4(v, __ldg(A4 + base + 3 * KC4));
        } else {
            v = __ldg(A4 + (size_t)(row0 + r) * KC4 + c4);
        }
        As2[(c4 * 4 + 0) * 64 + r] = pack2(v.x, v.x);
        As2[(c4 * 4 + 1) * 64 + r] = pack2(v.y, v.y);
        As2[(c4 * 4 + 2) * 64 + r] = pack2(v.z, v.z);
        As2[(c4 * 4 + 3) * 64 + r] = pack2(v.w, v.w);
    }
    // Stage B with on-the-fly transpose of w (scalar loads: input buffer)
    for (int idx = tid; idx < K * 144; idx += 288) {
        int c = idx / 144, cl = idx % 144;
        int g = col0 + cl;
        Bs[c * 144 + cl] = __ldg(w + (g % COUT) * (9 * K) + (g / COUT) * K + c);
    }
    __syncthreads();

    const int tx = tid % 18;   // 18 col-groups of 8
    const int ty = tid / 18;   // 16 row-groups of 4

    u64 acc[4][4];
#pragma unroll
    for (int r = 0; r < 4; r++)
#pragma unroll
        for (int j = 0; j < 4; j++) acc[r][j] = 0ull;

    // register double-buffer: fragments for kk while loading kk+1
    u64 ca[4], cb[4], na[4], nb[4];
    {
        const ulonglong2* ap = reinterpret_cast<const ulonglong2*>(&As2[0 * 64 + ty * 4]);
        ulonglong2 A0 = ap[0], A1 = ap[1];
        ca[0] = A0.x; ca[1] = A0.y; ca[2] = A1.x; ca[3] = A1.y;
        const ulonglong2* bp = reinterpret_cast<const ulonglong2*>(&Bs[0 * 144 + tx * 8]);
        ulonglong2 B0 = bp[0], B1 = bp[1];
        cb[0] = B0.x; cb[1] = B0.y; cb[2] = B1.x; cb[3] = B1.y;
    }

#pragma unroll 4
    for (int kk = 0; kk < K; kk++) {
        if (kk + 1 < K) {
            const ulonglong2* ap = reinterpret_cast<const ulonglong2*>(&As2[(kk + 1) * 64 + ty * 4]);
            ulonglong2 A0 = ap[0], A1 = ap[1];
            na[0] = A0.x; na[1] = A0.y; na[2] = A1.x; na[3] = A1.y;
            const ulonglong2* bp = reinterpret_cast<const ulonglong2*>(&Bs[(kk + 1) * 144 + tx * 8]);
            ulonglong2 B0 = bp[0], B1 = bp[1];
            nb[0] = B0.x; nb[1] = B0.y; nb[2] = B1.x; nb[3] = B1.y;
        }
#pragma unroll
        for (int r = 0; r < 4; r++)
#pragma unroll
            for (int j = 0; j < 4; j++)
                fma2(acc[r][j], ca[r], cb[j]);
#pragma unroll
        for (int j = 0; j < 4; j++) { ca[j] = na[j]; cb[j] = nb[j]; }
    }

#pragma unroll
    for (int r = 0; r < 4; r++) {
        float* dst = P + (size_t)(row0 + ty * 4 + r) * Ntot + col0 + tx * 8;
        *reinterpret_cast<ulonglong2*>(dst)     = make_ulonglong2(acc[r][0], acc[r][1]);
        *reinterpret_cast<ulonglong2*>(dst + 4) = make_ulonglong2(acc[r][2], acc[r][3]);
    }
}

// ---------------- channel-parallel gather-sum ----------------
// thread = (node, 4 channels); COUT/4 consecutive threads cover a node's tap row
// -> each node-tap read is one contiguous COUT*4B transaction.
template<int COUT, int SHIFT, bool RELU>
__global__ __launch_bounds__(256)
void gather_k(const float* __restrict__ P, const int* __restrict__ neigh,
              const float* __restrict__ bias, float* __restrict__ out)
{
    constexpr int NPT = COUT / 4;     // threads per node
    constexpr int NPB = 256 / NPT;    // nodes per block
    __shared__ int sn[NPB * 9];
    const int node0 = blockIdx.x * NPB;
    for (int idx = threadIdx.x; idx < NPB * 9; idx += 256)
        sn[idx] = __ldg(neigh + (size_t)node0 * 9 + idx);
    __syncthreads();

    const int il = threadIdx.x / NPT, c4 = threadIdx.x % NPT;
    const int i = node0 + il;

    float4 v[9];
#pragma unroll
    for (int k = 0; k < 9; k++) {
        int n = sn[il * 9 + k];
        if (n >= 0)
            v[k] = __ldg(reinterpret_cast<const float4*>(
                       P + (size_t)(n >> SHIFT) * (9 * COUT) + k * COUT) + c4);
        else
            v[k] = make_float4(0.f, 0.f, 0.f, 0.f);
    }

    // bias: scalar loads (input buffer; avoid 16B-alignment assumption)
    float4 acc = make_float4(__ldg(bias + c4 * 4),     __ldg(bias + c4 * 4 + 1),
                             __ldg(bias + c4 * 4 + 2), __ldg(bias + c4 * 4 + 3));
#pragma unroll
    for (int k = 0; k < 9; k++) {
        acc.x += v[k].x; acc.y += v[k].y; acc.z += v[k].z; acc.w += v[k].w;
    }
    if (RELU) {
        acc.x = fmaxf(acc.x, 0.f); acc.y = fmaxf(acc.y, 0.f);
        acc.z = fmaxf(acc.z, 0.f); acc.w = fmaxf(acc.w, 0.f);
    }
    reinterpret_cast<float4*>(out + (size_t)i * COUT)[c4] = acc;
}

// ---------------- dec2 gather + fused head partial products ----------------
// COUT=16, SHIFT=2. Computes x8d slice in registers (relu), then the 9 head
// dots, butterfly-reduced over the node's 4 lanes; writes P6[i][0..8].
__global__ __launch_bounds__(256)
void gather_head_k(const float* __restrict__ P, const int* __restrict__ neigh,
                   const float* __restrict__ bias, const float* __restrict__ wh,
                   float* __restrict__ P6)
{
    constexpr int NPT = 4, NPB = 64;
    __shared__ int sn[NPB * 9];
    __shared__ float swh[144];
    const int node0 = blockIdx.x * NPB;
    for (int idx = threadIdx.x; idx < NPB * 9; idx += 256)
        sn[idx] = __ldg(neigh + (size_t)node0 * 9 + idx);
    if (threadIdx.x < 144) swh[threadIdx.x] = __ldg(wh + threadIdx.x);
    __syncthreads();

    const int il = threadIdx.x / NPT, c4 = threadIdx.x % NPT;
    const int i = node0 + il;

    float4 v[9];
#pragma unroll
    for (int k = 0; k < 9; k++) {
        int n = sn[il * 9 + k];
        if (n >= 0)
            v[k] = __ldg(reinterpret_cast<const float4*>(
                       P + (size_t)(n >> 2) * 144 + k * 16) + c4);
        else
            v[k] = make_float4(0.f, 0.f, 0.f, 0.f);
    }

    float4 acc = make_float4(__ldg(bias + c4 * 4),     __ldg(bias + c4 * 4 + 1),
                             __ldg(bias + c4 * 4 + 2), __ldg(bias + c4 * 4 + 3));
#pragma unroll
    for (int k = 0; k < 9; k++) {
        acc.x += v[k].x; acc.y += v[k].y; acc.z += v[k].z; acc.w += v[k].w;
    }
    acc.x = fmaxf(acc.x, 0.f); acc.y = fmaxf(acc.y, 0.f);
    acc.z = fmaxf(acc.z, 0.f); acc.w = fmaxf(acc.w, 0.f);

    // head partial dots: p[k2] = dot(acc, w_head[k2*16 + c4*4 .. +3])
    float p[9];
#pragma unroll
    for (int k2 = 0; k2 < 9; k2++) {
        const float* wv = &swh[k2 * 16 + c4 * 4];
        p[k2] = acc.x * wv[0] + acc.y * wv[1] + acc.z * wv[2] + acc.w * wv[3];
    }
    // butterfly across the 4 lanes of this node (lane groups are warp-aligned)
#pragma unroll
    for (int k2 = 0; k2 < 9; k2++) {
        p[k2] += __shfl_xor_sync(0xffffffffu, p[k2], 1);
        p[k2] += __shfl_xor_sync(0xffffffffu, p[k2], 2);
    }
    float* dst = P6 + (size_t)i * 9;
    dst[c4]     = p[c4];
    dst[c4 + 4] = p[c4 + 4];
    if (c4 == 0) dst[8] = p[8];
}

// ---------------- enc1 + pool3->2 fused: thread = parent node in N2 ----------------
__global__ __launch_bounds__(256)
void enc1pool_k(const float* __restrict__ feat, const int* __restrict__ neigh,
                const float* __restrict__ w, const float* __restrict__ b,
                float* __restrict__ out /* x7p [N2][16] */)
{
    __shared__ float sw[160];
    if (threadIdx.x < 144) sw[threadIdx.x] = __ldg(w + threadIdx.x);
    else if (threadIdx.x < 160) sw[threadIdx.x] = __ldg(b + threadIdx.x - 144);
    __syncthreads();

    int p = blockIdx.x * 256 + threadIdx.x;
    int nb[36];
#pragma unroll
    for (int j = 0; j < 36; j++) nb[j] = __ldg(neigh + (size_t)p * 36 + j);

    float m[16];
#pragma unroll
    for (int o = 0; o < 16; o++) m[o] = 0.f;   // relu(max(s)) with floor 0

#pragma unroll
    for (int ch = 0; ch < 4; ch++) {
        float f[9];
#pragma unroll
        for (int k = 0; k < 9; k++) {
            int n = nb[ch * 9 + k];
            f[k] = (n >= 0) ? __ldg(feat + n) : 0.f;
        }
#pragma unroll
        for (int o = 0; o < 16; o++) {
            float s = sw[144 + o];
#pragma unroll
            for (int k = 0; k < 9; k++) s += f[k] * sw[o * 9 + k];
            m[o] = fmaxf(m[o], s);
        }
    }
    float4* op = reinterpret_cast<float4*>(out + (size_t)p * 16);
#pragma unroll
    for (int j = 0; j < 4; j++)
        op[j] = make_float4(m[4*j], m[4*j+1], m[4*j+2], m[4*j+3]);
}

// ---------------- head gather: out[i] = b + sum_k P6[n_k][k] ----------------
__global__ __launch_bounds__(256)
void head_g(const float* __restrict__ P6, const int* __restrict__ neigh,
            const float* __restrict__ b, float* __restrict__ out)
{
    int i = blockIdx.x * 256 + threadIdx.x;
    float acc = __ldg(b);
#pragma unroll
    for (int k = 0; k < 9; k++) {
        int n = __ldg(neigh + (size_t)i * 9 + k);
        if (n >= 0) acc += __ldg(P6 + (size_t)n * 9 + k);
    }
    out[i] = acc;
}

extern "C" void kernel_launch(void* const* d_in, const int* in_sizes, int n_in,
                              void* d_out, int out_size)
{
    const float* features = (const float*)d_in[0];
    const int* neighs3 = (const int*)d_in[4];
    const int* neighs2 = (const int*)d_in[5];
    const int* neighs1 = (const int*)d_in[6];
    const float* w_enc1 = (const float*)d_in[7];
    const float* b_enc1 = (const float*)d_in[8];
    const float* w_enc2 = (const float*)d_in[9];
    const float* b_enc2 = (const float*)d_in[10];
    const float* w_enc3 = (const float*)d_in[11];
    const float* b_enc3 = (const float*)d_in[12];
    const float* w_dec1 = (const float*)d_in[13];
    const float* b_dec1 = (const float*)d_in[14];
    const float* w_dec2 = (const float*)d_in[15];
    const float* b_dec2 = (const float*)d_in[16];
    const float* w_head = (const float*)d_in[17];
    const float* b_head = (const float*)d_in[18];
    float* out = (float*)d_out;

    float *x7p, *x7, *x6, *x7d, *P, *P6;
    cudaGetSymbolAddress((void**)&x7p, g_x7p);
    cudaGetSymbolAddress((void**)&x7,  g_x7);
    cudaGetSymbolAddress((void**)&x6,  g_x6);
    cudaGetSymbolAddress((void**)&x7d, g_x7d);
    cudaGetSymbolAddress((void**)&P,   g_P);
    cudaGetSymbolAddress((void**)&P6,  g_P6);

    // dynamic smem: K*64*8 (dup A) + K*144*4 (B)
    const int SM16 = 16 * 64 * 8 + 16 * 144 * 4;   // 17408
    const int SM32 = 32 * 64 * 8 + 32 * 144 * 4;   // 34816
    const int SM64 = 64 * 64 * 8 + 64 * 144 * 4;   // 69632
    cudaFuncSetAttribute(gemm_k<16, 32, false>, cudaFuncAttributeMaxDynamicSharedMemorySize, SM16);
    cudaFuncSetAttribute(gemm_k<32, 64, true>,  cudaFuncAttributeMaxDynamicSharedMemorySize, SM32);
    cudaFuncSetAttribute(gemm_k<64, 32, false>, cudaFuncAttributeMaxDynamicSharedMemorySize, SM64);
    cudaFuncSetAttribute(gemm_k<32, 16, false>, cudaFuncAttributeMaxDynamicSharedMemorySize, SM32);

    // enc1 + pool3->2 fused: features [N3,1] -> x7p [N2,16]
    enc1pool_k<<<N2 / 256, 256>>>(features, neighs3, w_enc1, b_enc1, x7p);
    // enc2: P = x7p[N2,16] @ B[16,288]; gather -> x7 [N2,32]
    gemm_k<16, 32, false><<<dim3(N2 / 64, 2), 288, SM16>>>(x7p, w_enc2, P, 288);
    gather_k<32, 0, true><<<N2 / 32, 256>>>(P, neighs2, b_enc2, x7);
    // enc3 (pool2->1 fused into A-stage): P = pool(x7)[N1,32] @ B[32,576]; gather -> x6 [N1,64]
    gemm_k<32, 64, true><<<dim3(N1 / 64, 4), 288, SM32>>>(x7, w_enc3, P, 576);
    gather_k<64, 0, true><<<N1 / 16, 256>>>(P, neighs1, b_enc3, x6);
    // dec1: P = x6[N1,64] @ B[64,288]; gather(unpool >>2) -> x7d [N2,32]
    gemm_k<64, 32, false><<<dim3(N1 / 64, 2), 288, SM64>>>(x6, w_dec1, P, 288);
    gather_k<32, 2, true><<<N2 / 32, 256>>>(P, neighs2, b_dec1, x7d);
    // dec2: P = x7d[N2,32] @ B[32,144]; gather(unpool >>2) + fused head dots -> P6 [N3,9]
    gemm_k<32, 16, false><<<dim3(N2 / 64, 1), 288, SM32>>>(x7d, w_dec2, P, 144);
    gather_head_k<<<N3 / 64, 256>>>(P, neighs3, b_dec2, w_head, P6);
    // head gather -> out [N3,1]
    head_g<<<N3 / 256, 256>>>(P6, neighs3, b_head, out);
}

// round 10
// speedup vs baseline: 1.1765x; 1.1765x over previous
#include <cuda_runtime.h>

#define N3 262144
#define N2 65536
#define N1 16384

typedef unsigned long long u64;

// ---------------- scratch (allocation-free) ----------------
__device__ float g_x7p[N2 * 16];
__device__ float g_x7 [N2 * 32];
__device__ float g_x6 [N1 * 64];
__device__ float g_x7d[N2 * 32];
__device__ float g_P  [N2 * 288];   // 75MB, reused by every P phase (max = enc2)
__device__ float g_P6 [N3 * 9];     // head partial products

__device__ __forceinline__ u64 pack2(float lo, float hi) {
    u64 r; asm("mov.b64 %0, {%1, %2};" : "=l"(r) : "f"(lo), "f"(hi)); return r;
}
__device__ __forceinline__ void fma2(u64& d, u64 a, u64 b) {
    asm("fma.rn.f32x2 %0, %1, %2, %0;" : "+l"(d) : "l"(a), "l"(b));
}
__device__ __forceinline__ float4 max4(float4 a, float4 b) {
    return make_float4(fmaxf(a.x,b.x), fmaxf(a.y,b.y), fmaxf(a.z,b.z), fmaxf(a.w,b.w));
}

// ---------------- GEMM: P[M x Ntot] = A[M x K] @ B[K x Ntot] ----------------
// B[c][g] = w[g%COUT][(g/COUT)*K + c]   (per-tap weight transpose, built in smem)
// APOOL: A row r = elementwise max of child rows 4r..4r+3 (fused quadpool; inputs >=0).
// Tile: TM=128 x TN=144, 288 threads, 8x8 per thread (f32x2 packed cols).
// A stored PLAIN in smem (transposed); (a,a) pairs built JIT via mov.b64 on the
// idle ALU pipe -> 64B LDS per thread per kk instead of 96B, regs ~90 -> 2 CTAs/SM.
template<int K, int COUT, bool APOOL>
__global__ __launch_bounds__(288, 2)
void gemm_k(const float* __restrict__ A, const float* __restrict__ w,
            float* __restrict__ P, int Ntot)
{
    extern __shared__ float smf[];
    float* As = smf;             // [K][128] plain floats, transposed
    float* Bs = smf + K * 128;   // [K][144]

    const int tid  = threadIdx.x;
    const int row0 = blockIdx.x * 128;
    const int col0 = blockIdx.y * 144;

    // Stage A transposed: As[c][r] = A[row0+r][c]  (A is our aligned scratch -> float4 safe)
    const float4* A4 = reinterpret_cast<const float4*>(A);
    const int KC4 = K / 4;
    for (int idx = tid; idx < 128 * KC4; idx += 288) {
        int r = idx / KC4, c4 = idx % KC4;
        float4 v;
        if (APOOL) {
            size_t base = (size_t)(row0 + r) * 4 * KC4 + c4;
            v = __ldg(A4 + base);
            v = max4(v, __ldg(A4 + base + KC4));
            v = max4(v, __ldg(A4 + base + 2 * KC4));
            v = max4(v, __ldg(A4 + base + 3 * KC4));
        } else {
            v = __ldg(A4 + (size_t)(row0 + r) * KC4 + c4);
        }
        As[(c4 * 4 + 0) * 128 + r] = v.x;
        As[(c4 * 4 + 1) * 128 + r] = v.y;
        As[(c4 * 4 + 2) * 128 + r] = v.z;
        As[(c4 * 4 + 3) * 128 + r] = v.w;
    }
    // Stage B with on-the-fly transpose of w (scalar loads: input buffer)
    for (int idx = tid; idx < K * 144; idx += 288) {
        int c = idx / 144, cl = idx % 144;
        int g = col0 + cl;
        Bs[c * 144 + cl] = __ldg(w + (g % COUT) * (9 * K) + (g / COUT) * K + c);
    }
    __syncthreads();

    const int tx = tid % 18;   // 18 col-groups of 8
    const int ty = tid / 18;   // 16 row-groups of 8

    u64 acc[8][4];
#pragma unroll
    for (int r = 0; r < 8; r++)
#pragma unroll
        for (int j = 0; j < 4; j++) acc[r][j] = 0ull;

#pragma unroll 4
    for (int kk = 0; kk < K; kk++) {
        // A fragment: 8 plain floats (2x LDS.128, broadcast across same-ty lanes)
        const float4* ap4 = reinterpret_cast<const float4*>(&As[kk * 128 + ty * 8]);
        float4 Af0 = ap4[0], Af1 = ap4[1];
        float a[8] = {Af0.x, Af0.y, Af0.z, Af0.w, Af1.x, Af1.y, Af1.z, Af1.w};
        // B fragment: 4 contiguous u64 pairs (2x LDS.128)
        const ulonglong2* bp = reinterpret_cast<const ulonglong2*>(&Bs[kk * 144 + tx * 8]);
        ulonglong2 B0 = bp[0], B1 = bp[1];
        u64 b2[4] = {B0.x, B0.y, B1.x, B1.y};
#pragma unroll
        for (int r = 0; r < 8; r++) {
            u64 ar = pack2(a[r], a[r]);   // JIT (a,a) pair on ALU pipe
#pragma unroll
            for (int j = 0; j < 4; j++)
                fma2(acc[r][j], ar, b2[j]);
        }
    }

#pragma unroll
    for (int r = 0; r < 8; r++) {
        float* dst = P + (size_t)(row0 + ty * 8 + r) * Ntot + col0 + tx * 8;
        *reinterpret_cast<ulonglong2*>(dst)     = make_ulonglong2(acc[r][0], acc[r][1]);
        *reinterpret_cast<ulonglong2*>(dst + 4) = make_ulonglong2(acc[r][2], acc[r][3]);
    }
}

// ---------------- channel-parallel gather-sum ----------------
// thread = (node, 4 channels); COUT/4 consecutive threads cover a node's tap row
// -> each node-tap read is one contiguous COUT*4B transaction.
template<int COUT, int SHIFT, bool RELU>
__global__ __launch_bounds__(256)
void gather_k(const float* __restrict__ P, const int* __restrict__ neigh,
              const float* __restrict__ bias, float* __restrict__ out)
{
    constexpr int NPT = COUT / 4;     // threads per node
    constexpr int NPB = 256 / NPT;    // nodes per block
    __shared__ int sn[NPB * 9];
    const int node0 = blockIdx.x * NPB;
    for (int idx = threadIdx.x; idx < NPB * 9; idx += 256)
        sn[idx] = __ldg(neigh + (size_t)node0 * 9 + idx);
    __syncthreads();

    const int il = threadIdx.x / NPT, c4 = threadIdx.x % NPT;
    const int i = node0 + il;

    float4 v[9];
#pragma unroll
    for (int k = 0; k < 9; k++) {
        int n = sn[il * 9 + k];
        if (n >= 0)
            v[k] = __ldg(reinterpret_cast<const float4*>(
                       P + (size_t)(n >> SHIFT) * (9 * COUT) + k * COUT) + c4);
        else
            v[k] = make_float4(0.f, 0.f, 0.f, 0.f);
    }

    // bias: scalar loads (input buffer; avoid 16B-alignment assumption)
    float4 acc = make_float4(__ldg(bias + c4 * 4),     __ldg(bias + c4 * 4 + 1),
                             __ldg(bias + c4 * 4 + 2), __ldg(bias + c4 * 4 + 3));
#pragma unroll
    for (int k = 0; k < 9; k++) {
        acc.x += v[k].x; acc.y += v[k].y; acc.z += v[k].z; acc.w += v[k].w;
    }
    if (RELU) {
        acc.x = fmaxf(acc.x, 0.f); acc.y = fmaxf(acc.y, 0.f);
        acc.z = fmaxf(acc.z, 0.f); acc.w = fmaxf(acc.w, 0.f);
    }
    reinterpret_cast<float4*>(out + (size_t)i * COUT)[c4] = acc;
}

// ---------------- dec2 gather + fused head partial products ----------------
// COUT=16, SHIFT=2. Computes x8d slice in registers (relu), then the 9 head
// dots, butterfly-reduced over the node's 4 lanes; writes P6[i][0..8].
__global__ __launch_bounds__(256)
void gather_head_k(const float* __restrict__ P, const int* __restrict__ neigh,
                   const float* __restrict__ bias, const float* __restrict__ wh,
                   float* __restrict__ P6)
{
    constexpr int NPT = 4, NPB = 64;
    __shared__ int sn[NPB * 9];
    __shared__ float swh[144];
    const int node0 = blockIdx.x * NPB;
    for (int idx = threadIdx.x; idx < NPB * 9; idx += 256)
        sn[idx] = __ldg(neigh + (size_t)node0 * 9 + idx);
    if (threadIdx.x < 144) swh[threadIdx.x] = __ldg(wh + threadIdx.x);
    __syncthreads();

    const int il = threadIdx.x / NPT, c4 = threadIdx.x % NPT;
    const int i = node0 + il;

    float4 v[9];
#pragma unroll
    for (int k = 0; k < 9; k++) {
        int n = sn[il * 9 + k];
        if (n >= 0)
            v[k] = __ldg(reinterpret_cast<const float4*>(
                       P + (size_t)(n >> 2) * 144 + k * 16) + c4);
        else
            v[k] = make_float4(0.f, 0.f, 0.f, 0.f);
    }

    float4 acc = make_float4(__ldg(bias + c4 * 4),     __ldg(bias + c4 * 4 + 1),
                             __ldg(bias + c4 * 4 + 2), __ldg(bias + c4 * 4 + 3));
#pragma unroll
    for (int k = 0; k < 9; k++) {
        acc.x += v[k].x; acc.y += v[k].y; acc.z += v[k].z; acc.w += v[k].w;
    }
    acc.x = fmaxf(acc.x, 0.f); acc.y = fmaxf(acc.y, 0.f);
    acc.z = fmaxf(acc.z, 0.f); acc.w = fmaxf(acc.w, 0.f);

    // head partial dots: p[k2] = dot(acc, w_head[k2*16 + c4*4 .. +3])
    float p[9];
#pragma unroll
    for (int k2 = 0; k2 < 9; k2++) {
        const float* wv = &swh[k2 * 16 + c4 * 4];
        p[k2] = acc.x * wv[0] + acc.y * wv[1] + acc.z * wv[2] + acc.w * wv[3];
    }
    // butterfly across the 4 lanes of this node (lane groups are warp-aligned)
#pragma unroll
    for (int k2 = 0; k2 < 9; k2++) {
        p[k2] += __shfl_xor_sync(0xffffffffu, p[k2], 1);
        p[k2] += __shfl_xor_sync(0xffffffffu, p[k2], 2);
    }
    float* dst = P6 + (size_t)i * 9;
    dst[c4]     = p[c4];
    dst[c4 + 4] = p[c4 + 4];
    if (c4 == 0) dst[8] = p[8];
}

// ---------------- enc1 + pool3->2 fused: thread = parent node in N2 ----------------
__global__ __launch_bounds__(256)
void enc1pool_k(const float* __restrict__ feat, const int* __restrict__ neigh,
                const float* __restrict__ w, const float* __restrict__ b,
                float* __restrict__ out /* x7p [N2][16] */)
{
    __shared__ float sw[160];
    if (threadIdx.x < 144) sw[threadIdx.x] = __ldg(w + threadIdx.x);
    else if (threadIdx.x < 160) sw[threadIdx.x] = __ldg(b + threadIdx.x - 144);
    __syncthreads();

    int p = blockIdx.x * 256 + threadIdx.x;
    int nb[36];
#pragma unroll
    for (int j = 0; j < 36; j++) nb[j] = __ldg(neigh + (size_t)p * 36 + j);

    float m[16];
#pragma unroll
    for (int o = 0; o < 16; o++) m[o] = 0.f;   // relu(max(s)) with floor 0

#pragma unroll
    for (int ch = 0; ch < 4; ch++) {
        float f[9];
#pragma unroll
        for (int k = 0; k < 9; k++) {
            int n = nb[ch * 9 + k];
            f[k] = (n >= 0) ? __ldg(feat + n) : 0.f;
        }
#pragma unroll
        for (int o = 0; o < 16; o++) {
            float s = sw[144 + o];
#pragma unroll
            for (int k = 0; k < 9; k++) s += f[k] * sw[o * 9 + k];
            m[o] = fmaxf(m[o], s);
        }
    }
    float4* op = reinterpret_cast<float4*>(out + (size_t)p * 16);
#pragma unroll
    for (int j = 0; j < 4; j++)
        op[j] = make_float4(m[4*j], m[4*j+1], m[4*j+2], m[4*j+3]);
}

// ---------------- head gather: out[i] = b + sum_k P6[n_k][k] ----------------
__global__ __launch_bounds__(256)
void head_g(const float* __restrict__ P6, const int* __restrict__ neigh,
            const float* __restrict__ b, float* __restrict__ out)
{
    int i = blockIdx.x * 256 + threadIdx.x;
    float acc = __ldg(b);
#pragma unroll
    for (int k = 0; k < 9; k++) {
        int n = __ldg(neigh + (size_t)i * 9 + k);
        if (n >= 0) acc += __ldg(P6 + (size_t)n * 9 + k);
    }
    out[i] = acc;
}

extern "C" void kernel_launch(void* const* d_in, const int* in_sizes, int n_in,
                              void* d_out, int out_size)
{
    const float* features = (const float*)d_in[0];
    const int* neighs3 = (const int*)d_in[4];
    const int* neighs2 = (const int*)d_in[5];
    const int* neighs1 = (const int*)d_in[6];
    const float* w_enc1 = (const float*)d_in[7];
    const float* b_enc1 = (const float*)d_in[8];
    const float* w_enc2 = (const float*)d_in[9];
    const float* b_enc2 = (const float*)d_in[10];
    const float* w_enc3 = (const float*)d_in[11];
    const float* b_enc3 = (const float*)d_in[12];
    const float* w_dec1 = (const float*)d_in[13];
    const float* b_dec1 = (const float*)d_in[14];
    const float* w_dec2 = (const float*)d_in[15];
    const float* b_dec2 = (const float*)d_in[16];
    const float* w_head = (const float*)d_in[17];
    const float* b_head = (const float*)d_in[18];
    float* out = (float*)d_out;

    float *x7p, *x7, *x6, *x7d, *P, *P6;
    cudaGetSymbolAddress((void**)&x7p, g_x7p);
    cudaGetSymbolAddress((void**)&x7,  g_x7);
    cudaGetSymbolAddress((void**)&x6,  g_x6);
    cudaGetSymbolAddress((void**)&x7d, g_x7d);
    cudaGetSymbolAddress((void**)&P,   g_P);
    cudaGetSymbolAddress((void**)&P6,  g_P6);

    // dynamic smem: K*128*4 (plain A) + K*144*4 (B)
    const int SM16 = 16 * 128 * 4 + 16 * 144 * 4;   // 17408
    const int SM32 = 32 * 128 * 4 + 32 * 144 * 4;   // 34816
    const int SM64 = 64 * 128 * 4 + 64 * 144 * 4;   // 69632
    cudaFuncSetAttribute(gemm_k<16, 32, false>, cudaFuncAttributeMaxDynamicSharedMemorySize, SM16);
    cudaFuncSetAttribute(gemm_k<32, 64, true>,  cudaFuncAttributeMaxDynamicSharedMemorySize, SM32);
    cudaFuncSetAttribute(gemm_k<64, 32, false>, cudaFuncAttributeMaxDynamicSharedMemorySize, SM64);
    cudaFuncSetAttribute(gemm_k<32, 16, false>, cudaFuncAttributeMaxDynamicSharedMemorySize, SM32);

    // enc1 + pool3->2 fused: features [N3,1] -> x7p [N2,16]
    enc1pool_k<<<N2 / 256, 256>>>(features, neighs3, w_enc1, b_enc1, x7p);
    // enc2: P = x7p[N2,16] @ B[16,288]; gather -> x7 [N2,32]
    gemm_k<16, 32, false><<<dim3(N2 / 128, 2), 288, SM16>>>(x7p, w_enc2, P, 288);
    gather_k<32, 0, true><<<N2 / 32, 256>>>(P, neighs2, b_enc2, x7);
    // enc3 (pool2->1 fused into A-stage): P = pool(x7)[N1,32] @ B[32,576]; gather -> x6 [N1,64]
    gemm_k<32, 64, true><<<dim3(N1 / 128, 4), 288, SM32>>>(x7, w_enc3, P, 576);
    gather_k<64, 0, true><<<N1 / 16, 256>>>(P, neighs1, b_enc3, x6);
    // dec1: P = x6[N1,64] @ B[64,288]; gather(unpool >>2) -> x7d [N2,32]
    gemm_k<64, 32, false><<<dim3(N1 / 128, 2), 288, SM64>>>(x6, w_dec1, P, 288);
    gather_k<32, 2, true><<<N2 / 32, 256>>>(P, neighs2, b_dec1, x7d);
    // dec2: P = x7d[N2,32] @ B[32,144]; gather(unpool >>2) + fused head dots -> P6 [N3,9]
    gemm_k<32, 16, false><<<dim3(N2 / 128, 1), 288, SM32>>>(x7d, w_dec2, P, 144);
    gather_head_k<<<N3 / 64, 256>>>(P, neighs3, b_dec2, w_head, P6);
    // head gather -> out [N3,1]
    head_g<<<N3 / 256, 256>>>(P6, neighs3, b_head, out);
}

// round 11
// speedup vs baseline: 1.4725x; 1.2516x over previous
#include <cuda_runtime.h>

#define N3 262144
#define N2 65536
#define N1 16384

typedef unsigned long long u64;

// ---------------- scratch (allocation-free) ----------------
__device__ float g_x7p[N2 * 16];
__device__ float g_x7 [N2 * 32];
__device__ float g_x6 [N1 * 64];
__device__ float g_x7d[N2 * 32];
__device__ float g_P  [N2 * 288];   // 75MB, reused by every P phase (max = enc2)
__device__ float g_P6 [N3 * 9];     // head partial products

__device__ __forceinline__ u64 pack2(float lo, float hi) {
    u64 r; asm("mov.b64 %0, {%1, %2};" : "=l"(r) : "f"(lo), "f"(hi)); return r;
}
__device__ __forceinline__ void fma2(u64& d, u64 a, u64 b) {
    asm("fma.rn.f32x2 %0, %1, %2, %0;" : "+l"(d) : "l"(a), "l"(b));
}
__device__ __forceinline__ float4 max4(float4 a, float4 b) {
    return make_float4(fmaxf(a.x,b.x), fmaxf(a.y,b.y), fmaxf(a.z,b.z), fmaxf(a.w,b.w));
}

// ---------------- GEMM: P[M x Ntot] = A[M x K] @ B[K x Ntot] ----------------
// B[c][g] = w[g%COUT][(g/COUT)*K + c]   (per-tap weight transpose, built in smem)
// APOOL: A row r = elementwise max of child rows 4r..4r+3 (fused quadpool; inputs >=0).
// Tile: TM=128 x TN=144, 288 threads, 8 rows x 4 f32x2-col-pairs per thread.
// Thread tx owns col pairs (2tx + 36m), m=0..3 -> B LDS at 8B lane stride
// (conflict degree <=2 instead of 5 for the old contiguous 32B-stride fragment).
// A stored plain (transposed); (a,a) pairs built JIT via mov.b64 on the ALU pipe.
template<int K, int COUT, bool APOOL>
__global__ __launch_bounds__(288, 2)
void gemm_k(const float* __restrict__ A, const float* __restrict__ w,
            float* __restrict__ P, int Ntot)
{
    extern __shared__ float smf[];
    float* As = smf;             // [K][128] plain floats, transposed
    float* Bs = smf + K * 128;   // [K][144]

    const int tid  = threadIdx.x;
    const int row0 = blockIdx.x * 128;
    const int col0 = blockIdx.y * 144;

    // Stage A transposed: As[c][r] = A[row0+r][c]  (A is our aligned scratch -> float4 safe)
    const float4* A4 = reinterpret_cast<const float4*>(A);
    const int KC4 = K / 4;
    for (int idx = tid; idx < 128 * KC4; idx += 288) {
        int r = idx / KC4, c4 = idx % KC4;
        float4 v;
        if (APOOL) {
            size_t base = (size_t)(row0 + r) * 4 * KC4 + c4;
            v = __ldg(A4 + base);
            v = max4(v, __ldg(A4 + base + KC4));
            v = max4(v, __ldg(A4 + base + 2 * KC4));
            v = max4(v, __ldg(A4 + base + 3 * KC4));
        } else {
            v = __ldg(A4 + (size_t)(row0 + r) * KC4 + c4);
        }
        As[(c4 * 4 + 0) * 128 + r] = v.x;
        As[(c4 * 4 + 1) * 128 + r] = v.y;
        As[(c4 * 4 + 2) * 128 + r] = v.z;
        As[(c4 * 4 + 3) * 128 + r] = v.w;
    }
    // Stage B with on-the-fly transpose of w (scalar loads: input buffer)
    for (int idx = tid; idx < K * 144; idx += 288) {
        int c = idx / 144, cl = idx % 144;
        int g = col0 + cl;
        Bs[c * 144 + cl] = __ldg(w + (g % COUT) * (9 * K) + (g / COUT) * K + c);
    }
    __syncthreads();

    const int tx = tid % 18;   // col-pair owner: cols 2tx+36m, m=0..3
    const int ty = tid / 18;   // 16 row-groups of 8

    u64 acc[8][4];
#pragma unroll
    for (int r = 0; r < 8; r++)
#pragma unroll
        for (int j = 0; j < 4; j++) acc[r][j] = 0ull;

#pragma unroll 4
    for (int kk = 0; kk < K; kk++) {
        // A fragment: 8 plain floats (2x LDS.128, broadcast across same-ty lanes)
        const float4* ap4 = reinterpret_cast<const float4*>(&As[kk * 128 + ty * 8]);
        float4 Af0 = ap4[0], Af1 = ap4[1];
        float a[8] = {Af0.x, Af0.y, Af0.z, Af0.w, Af1.x, Af1.y, Af1.z, Af1.w};
        // B fragment: 4 f32x2 pairs at cols 2tx+36m -> LDS.64, 8B lane stride
        const float* brow = &Bs[kk * 144 + tx * 2];
        u64 b2[4];
#pragma unroll
        for (int m = 0; m < 4; m++)
            b2[m] = *reinterpret_cast<const u64*>(brow + m * 36);
#pragma unroll
        for (int r = 0; r < 8; r++) {
            u64 ar = pack2(a[r], a[r]);   // JIT (a,a) pair on ALU pipe
#pragma unroll
            for (int j = 0; j < 4; j++)
                fma2(acc[r][j], ar, b2[j]);
        }
    }

#pragma unroll
    for (int r = 0; r < 8; r++) {
        float* dst = P + (size_t)(row0 + ty * 8 + r) * Ntot + col0 + tx * 2;
#pragma unroll
        for (int m = 0; m < 4; m++)
            *reinterpret_cast<u64*>(dst + m * 36) = acc[r][m];
    }
}

// ---------------- channel-parallel gather-sum ----------------
// thread = (node, 4 channels); COUT/4 consecutive threads cover a node's tap row
// -> each node-tap read is one contiguous COUT*4B transaction.
template<int COUT, int SHIFT, bool RELU>
__global__ __launch_bounds__(256)
void gather_k(const float* __restrict__ P, const int* __restrict__ neigh,
              const float* __restrict__ bias, float* __restrict__ out)
{
    constexpr int NPT = COUT / 4;     // threads per node
    constexpr int NPB = 256 / NPT;    // nodes per block
    __shared__ int sn[NPB * 9];
    const int node0 = blockIdx.x * NPB;
    for (int idx = threadIdx.x; idx < NPB * 9; idx += 256)
        sn[idx] = __ldg(neigh + (size_t)node0 * 9 + idx);
    __syncthreads();

    const int il = threadIdx.x / NPT, c4 = threadIdx.x % NPT;
    const int i = node0 + il;

    float4 v[9];
#pragma unroll
    for (int k = 0; k < 9; k++) {
        int n = sn[il * 9 + k];
        if (n >= 0)
            v[k] = __ldg(reinterpret_cast<const float4*>(
                       P + (size_t)(n >> SHIFT) * (9 * COUT) + k * COUT) + c4);
        else
            v[k] = make_float4(0.f, 0.f, 0.f, 0.f);
    }

    // bias: scalar loads (input buffer; avoid 16B-alignment assumption)
    float4 acc = make_float4(__ldg(bias + c4 * 4),     __ldg(bias + c4 * 4 + 1),
                             __ldg(bias + c4 * 4 + 2), __ldg(bias + c4 * 4 + 3));
#pragma unroll
    for (int k = 0; k < 9; k++) {
        acc.x += v[k].x; acc.y += v[k].y; acc.z += v[k].z; acc.w += v[k].w;
    }
    if (RELU) {
        acc.x = fmaxf(acc.x, 0.f); acc.y = fmaxf(acc.y, 0.f);
        acc.z = fmaxf(acc.z, 0.f); acc.w = fmaxf(acc.w, 0.f);
    }
    reinterpret_cast<float4*>(out + (size_t)i * COUT)[c4] = acc;
}

// ---------------- dec2 gather + fused head partial products ----------------
// COUT=16, SHIFT=2. Computes x8d slice in registers (relu), then the 9 head
// dots, butterfly-reduced over the node's 4 lanes; writes P6[i][0..8].
__global__ __launch_bounds__(256)
void gather_head_k(const float* __restrict__ P, const int* __restrict__ neigh,
                   const float* __restrict__ bias, const float* __restrict__ wh,
                   float* __restrict__ P6)
{
    constexpr int NPT = 4, NPB = 64;
    __shared__ int sn[NPB * 9];
    __shared__ float swh[144];
    const int node0 = blockIdx.x * NPB;
    for (int idx = threadIdx.x; idx < NPB * 9; idx += 256)
        sn[idx] = __ldg(neigh + (size_t)node0 * 9 + idx);
    if (threadIdx.x < 144) swh[threadIdx.x] = __ldg(wh + threadIdx.x);
    __syncthreads();

    const int il = threadIdx.x / NPT, c4 = threadIdx.x % NPT;
    const int i = node0 + il;

    float4 v[9];
#pragma unroll
    for (int k = 0; k < 9; k++) {
        int n = sn[il * 9 + k];
        if (n >= 0)
            v[k] = __ldg(reinterpret_cast<const float4*>(
                       P + (size_t)(n >> 2) * 144 + k * 16) + c4);
        else
            v[k] = make_float4(0.f, 0.f, 0.f, 0.f);
    }

    float4 acc = make_float4(__ldg(bias + c4 * 4),     __ldg(bias + c4 * 4 + 1),
                             __ldg(bias + c4 * 4 + 2), __ldg(bias + c4 * 4 + 3));
#pragma unroll
    for (int k = 0; k < 9; k++) {
        acc.x += v[k].x; acc.y += v[k].y; acc.z += v[k].z; acc.w += v[k].w;
    }
    acc.x = fmaxf(acc.x, 0.f); acc.y = fmaxf(acc.y, 0.f);
    acc.z = fmaxf(acc.z, 0.f); acc.w = fmaxf(acc.w, 0.f);

    // head partial dots: p[k2] = dot(acc, w_head[k2*16 + c4*4 .. +3])
    float p[9];
#pragma unroll
    for (int k2 = 0; k2 < 9; k2++) {
        const float* wv = &swh[k2 * 16 + c4 * 4];
        p[k2] = acc.x * wv[0] + acc.y * wv[1] + acc.z * wv[2] + acc.w * wv[3];
    }
    // butterfly across the 4 lanes of this node (lane groups are warp-aligned)
#pragma unroll
    for (int k2 = 0; k2 < 9; k2++) {
        p[k2] += __shfl_xor_sync(0xffffffffu, p[k2], 1);
        p[k2] += __shfl_xor_sync(0xffffffffu, p[k2], 2);
    }
    float* dst = P6 + (size_t)i * 9;
    dst[c4]     = p[c4];
    dst[c4 + 4] = p[c4 + 4];
    if (c4 == 0) dst[8] = p[8];
}

// ---------------- enc1 + pool3->2 fused: thread = parent node in N2 ----------------
__global__ __launch_bounds__(256)
void enc1pool_k(const float* __restrict__ feat, const int* __restrict__ neigh,
                const float* __restrict__ w, const float* __restrict__ b,
                float* __restrict__ out /* x7p [N2][16] */)
{
    __shared__ float sw[160];
    if (threadIdx.x < 144) sw[threadIdx.x] = __ldg(w + threadIdx.x);
    else if (threadIdx.x < 160) sw[threadIdx.x] = __ldg(b + threadIdx.x - 144);
    __syncthreads();

    int p = blockIdx.x * 256 + threadIdx.x;
    int nb[36];
#pragma unroll
    for (int j = 0; j < 36; j++) nb[j] = __ldg(neigh + (size_t)p * 36 + j);

    float m[16];
#pragma unroll
    for (int o = 0; o < 16; o++) m[o] = 0.f;   // relu(max(s)) with floor 0

#pragma unroll
    for (int ch = 0; ch < 4; ch++) {
        float f[9];
#pragma unroll
        for (int k = 0; k < 9; k++) {
            int n = nb[ch * 9 + k];
            f[k] = (n >= 0) ? __ldg(feat + n) : 0.f;
        }
#pragma unroll
        for (int o = 0; o < 16; o++) {
            float s = sw[144 + o];
#pragma unroll
            for (int k = 0; k < 9; k++) s += f[k] * sw[o * 9 + k];
            m[o] = fmaxf(m[o], s);
        }
    }
    float4* op = reinterpret_cast<float4*>(out + (size_t)p * 16);
#pragma unroll
    for (int j = 0; j < 4; j++)
        op[j] = make_float4(m[4*j], m[4*j+1], m[4*j+2], m[4*j+3]);
}

// ---------------- head gather: out[i] = b + sum_k P6[n_k][k] ----------------
__global__ __launch_bounds__(256)
void head_g(const float* __restrict__ P6, const int* __restrict__ neigh,
            const float* __restrict__ b, float* __restrict__ out)
{
    int i = blockIdx.x * 256 + threadIdx.x;
    float acc = __ldg(b);
#pragma unroll
    for (int k = 0; k < 9; k++) {
        int n = __ldg(neigh + (size_t)i * 9 + k);
        if (n >= 0) acc += __ldg(P6 + (size_t)n * 9 + k);
    }
    out[i] = acc;
}

extern "C" void kernel_launch(void* const* d_in, const int* in_sizes, int n_in,
                              void* d_out, int out_size)
{
    const float* features = (const float*)d_in[0];
    const int* neighs3 = (const int*)d_in[4];
    const int* neighs2 = (const int*)d_in[5];
    const int* neighs1 = (const int*)d_in[6];
    const float* w_enc1 = (const float*)d_in[7];
    const float* b_enc1 = (const float*)d_in[8];
    const float* w_enc2 = (const float*)d_in[9];
    const float* b_enc2 = (const float*)d_in[10];
    const float* w_enc3 = (const float*)d_in[11];
    const float* b_enc3 = (const float*)d_in[12];
    const float* w_dec1 = (const float*)d_in[13];
    const float* b_dec1 = (const float*)d_in[14];
    const float* w_dec2 = (const float*)d_in[15];
    const float* b_dec2 = (const float*)d_in[16];
    const float* w_head = (const float*)d_in[17];
    const float* b_head = (const float*)d_in[18];
    float* out = (float*)d_out;

    float *x7p, *x7, *x6, *x7d, *P, *P6;
    cudaGetSymbolAddress((void**)&x7p, g_x7p);
    cudaGetSymbolAddress((void**)&x7,  g_x7);
    cudaGetSymbolAddress((void**)&x6,  g_x6);
    cudaGetSymbolAddress((void**)&x7d, g_x7d);
    cudaGetSymbolAddress((void**)&P,   g_P);
    cudaGetSymbolAddress((void**)&P6,  g_P6);

    // dynamic smem: K*128*4 (plain A) + K*144*4 (B)
    const int SM16 = 16 * 128 * 4 + 16 * 144 * 4;   // 17408
    const int SM32 = 32 * 128 * 4 + 32 * 144 * 4;   // 34816
    const int SM64 = 64 * 128 * 4 + 64 * 144 * 4;   // 69632
    cudaFuncSetAttribute(gemm_k<16, 32, false>, cudaFuncAttributeMaxDynamicSharedMemorySize, SM16);
    cudaFuncSetAttribute(gemm_k<32, 64, true>,  cudaFuncAttributeMaxDynamicSharedMemorySize, SM32);
    cudaFuncSetAttribute(gemm_k<64, 32, false>, cudaFuncAttributeMaxDynamicSharedMemorySize, SM64);
    cudaFuncSetAttribute(gemm_k<32, 16, false>, cudaFuncAttributeMaxDynamicSharedMemorySize, SM32);

    // enc1 + pool3->2 fused: features [N3,1] -> x7p [N2,16]
    enc1pool_k<<<N2 / 256, 256>>>(features, neighs3, w_enc1, b_enc1, x7p);
    // enc2: P = x7p[N2,16] @ B[16,288]; gather -> x7 [N2,32]
    gemm_k<16, 32, false><<<dim3(N2 / 128, 2), 288, SM16>>>(x7p, w_enc2, P, 288);
    gather_k<32, 0, true><<<N2 / 32, 256>>>(P, neighs2, b_enc2, x7);
    // enc3 (pool2->1 fused into A-stage): P = pool(x7)[N1,32] @ B[32,576]; gather -> x6 [N1,64]
    gemm_k<32, 64, true><<<dim3(N1 / 128, 4), 288, SM32>>>(x7, w_enc3, P, 576);
    gather_k<64, 0, true><<<N1 / 16, 256>>>(P, neighs1, b_enc3, x6);
    // dec1: P = x6[N1,64] @ B[64,288]; gather(unpool >>2) -> x7d [N2,32]
    gemm_k<64, 32, false><<<dim3(N1 / 128, 2), 288, SM64>>>(x6, w_dec1, P, 288);
    gather_k<32, 2, true><<<N2 / 32, 256>>>(P, neighs2, b_dec1, x7d);
    // dec2: P = x7d[N2,32] @ B[32,144]; gather(unpool >>2) + fused head dots -> P6 [N3,9]
    gemm_k<32, 16, false><<<dim3(N2 / 128, 1), 288, SM32>>>(x7d, w_dec2, P, 144);
    gather_head_k<<<N3 / 64, 256>>>(P, neighs3, b_dec2, w_head, P6);
    // head gather -> out [N3,1]
    head_g<<<N3 / 256, 256>>>(P6, neighs3, b_head, out);
}